// round 15
// baseline (speedup 1.0000x reference)
#include <cuda_runtime.h>
#include <cuda_fp16.h>
#include <cstdint>
#include <cstddef>

// ---------------------------------------------------------------------------
// Problem constants
// ---------------------------------------------------------------------------
constexpr int NN  = 8192;   // nodes
constexpr int FIN = 256;    // input features
constexpr int HC  = 128;    // fused hidden columns (h1 | h2)

// GEMM tiling (R9-validated, DO NOT TOUCH): BM=64 BN=128 BK=32, 256 thr
constexpr int BM = 64, BN = 128, BKk = 32;
constexpr int KHALF = NN / 2;           // 4096
constexpr int NT = KHALF / BKk;         // 128 iters
constexpr int NBANDS = NN / BM;         // 128 row bands
constexpr int ROWB = 80;                // padded smem row stride (bytes)
constexpr int OA = 0;
constexpr int OB = BM * ROWB;           // 5120
constexpr int STAGE = OB + BN * ROWB;   // 15360 bytes / stage
constexpr int NSTG = 3;
constexpr int DYN_SMEM = NSTG * STAGE + 256;

constexpr float ASCALE   = 8192.0f;     // exact pow2: adj*ASCALE in (0,1) for fp16
constexpr float ASCALE_I = 1.0f / 8192.0f;

// ---------------------------------------------------------------------------
// Device scratch (allocation-free per harness rules)
// ---------------------------------------------------------------------------
__device__ unsigned short g_bh[HC * NN];    // fts^T fp16 [n][k]
__device__ float g_acc0[NN * HC];           // K-half 0 partial (scaled by 8192)
__device__ float g_acc1[NN * HC];           // K-half 1 partial
__device__ float g_h[NN * HC];              // h1|h2 after bias+PReLU
__device__ float g_part[128 * 64];          // per-band colsums of h1*msk
__device__ float g_mskpart[128];            // per-band msk sums
__device__ float g_wc[64];                  // disc_w @ sigmoid(c)
__device__ int   g_bandctr[NBANDS];         // per-band completion tickets
__device__ int   g_epictr;                  // global band-epilogue ticket

// ---------------------------------------------------------------------------
// Helpers (baseline PTX only — compute_103 virtual target safe)
// ---------------------------------------------------------------------------
using u64 = unsigned long long;

__device__ __forceinline__ uint32_t smem_u32(const void* p) {
    uint32_t r;
    asm("{ .reg .u64 t; cvta.to.shared.u64 t, %1; cvt.u32.u64 %0, t; }"
        : "=r"(r) : "l"(p));
    return r;
}
__device__ __forceinline__ uint32_t pkhf(float lo, float hi) {
    __half2 h = __floats2half2_rn(lo, hi);
    return *reinterpret_cast<uint32_t*>(&h);
}
__device__ __forceinline__ u64 pk2(float x, float y) {
    u64 r; asm("mov.b64 %0, {%1,%2};" : "=l"(r) : "f"(x), "f"(y)); return r;
}
__device__ __forceinline__ float2 unpk(u64 v) {
    float2 r; asm("mov.b64 {%0,%1}, %2;" : "=f"(r.x), "=f"(r.y) : "l"(v)); return r;
}
__device__ __forceinline__ void fma2(u64& d, u64 a, u64 b) {
    asm("fma.rn.f32x2 %0, %1, %2, %0;" : "+l"(d) : "l"(a), "l"(b));
}
__device__ __forceinline__ void sts64(uint32_t addr, uint32_t a, uint32_t b) {
    asm volatile("st.shared.v2.b32 [%0], {%1, %2};"
                 :: "r"(addr), "r"(a), "r"(b) : "memory");
}
__device__ __forceinline__ void ldm4(uint32_t* r, uint32_t addr) {
    asm volatile("ldmatrix.sync.aligned.m8n8.x4.shared.b16 {%0,%1,%2,%3}, [%4];"
                 : "=r"(r[0]), "=r"(r[1]), "=r"(r[2]), "=r"(r[3]) : "r"(addr));
}
__device__ __forceinline__ void mma16816(float* c, const uint32_t* a,
                                         uint32_t b0, uint32_t b1) {
    asm volatile(
        "mma.sync.aligned.m16n8k16.row.col.f32.f16.f16.f32 "
        "{%0,%1,%2,%3}, {%4,%5,%6,%7}, {%8,%9}, {%0,%1,%2,%3};"
        : "+f"(c[0]), "+f"(c[1]), "+f"(c[2]), "+f"(c[3])
        : "r"(a[0]), "r"(a[1]), "r"(a[2]), "r"(a[3]), "r"(b0), "r"(b1));
}
__device__ __forceinline__ void cpa16(uint32_t dst, const void* src) {
    asm volatile("cp.async.cg.shared.global [%0], [%1], 16;"
                 :: "r"(dst), "l"(src));
}
__device__ __forceinline__ void cp_commit() {
    asm volatile("cp.async.commit_group;" ::: "memory");
}
__device__ __forceinline__ void cp_wait1() {
    asm volatile("cp.async.wait_group 1;" ::: "memory");
}

// ---------------------------------------------------------------------------
// Kernel 1: fts = seq@W^T (both seqs); emit fp16 TRANSPOSED [n][k].
// f32x2-packed compute (validated R14). Also resets all tickets.
// ---------------------------------------------------------------------------
__global__ void __launch_bounds__(128) fts_kernel(
    const float* __restrict__ seq1, const float* __restrict__ seq2,
    const float* __restrict__ fcw) {
    __shared__ float wt[64][64];    // transposed fc_w chunk [f_local][h]
    __shared__ float s1[16][64];
    __shared__ float s2[16][64];

    if (blockIdx.x == 0) {
        if (threadIdx.x == 0) g_epictr = 0;
        if (threadIdx.x < NBANDS) g_bandctr[threadIdx.x] = 0;
    }

    const int tid = threadIdx.x;
    const int m0 = blockIdx.x * 16;
    const int id = tid & 63;
    const int cg = id & 15;
    const int rg = id >> 4;
    const int j0 = cg * 4;
    const int r0 = rg * 4;
    const int nbase = (tid < 64) ? 0 : 64;

    u64 acc2[4][2];
#pragma unroll
    for (int i = 0; i < 4; ++i) { acc2[i][0] = 0ull; acc2[i][1] = 0ull; }

    for (int fc = 0; fc < 4; ++fc) {
        const int f0 = fc * 64;
        __syncthreads();
        {
            const int row = tid & 63, half = tid >> 6;
#pragma unroll
            for (int p = 0; p < 8; ++p) {
                const int c = half * 8 + p;
                float4 v = *(const float4*)&fcw[row * FIN + f0 + c * 4];
                wt[c * 4 + 0][row] = v.x;
                wt[c * 4 + 1][row] = v.y;
                wt[c * 4 + 2][row] = v.z;
                wt[c * 4 + 3][row] = v.w;
            }
        }
#pragma unroll
        for (int p = 0; p < 2; ++p) {
            const int idx = tid + 128 * p;
            const int r = idx >> 4, c4 = idx & 15;
            *(float4*)&s1[r][c4 * 4] = *(const float4*)&seq1[(size_t)(m0 + r) * FIN + f0 + c4 * 4];
            *(float4*)&s2[r][c4 * 4] = *(const float4*)&seq2[(size_t)(m0 + r) * FIN + f0 + c4 * 4];
        }
        __syncthreads();

        const float (*sp)[64] = (tid < 64) ? s1 : s2;
#pragma unroll 4
        for (int f = 0; f < 64; ++f) {
            const float2 wa = *(const float2*)&wt[f][j0];
            const float2 wb = *(const float2*)&wt[f][j0 + 2];
            const u64 w01 = pk2(wa.x, wa.y);
            const u64 w23 = pk2(wb.x, wb.y);
#pragma unroll
            for (int i = 0; i < 4; ++i) {
                const float a = sp[r0 + i][f];
                const u64 aa = pk2(a, a);
                fma2(acc2[i][0], aa, w01);
                fma2(acc2[i][1], aa, w23);
            }
        }
    }

    float v[4][4];
#pragma unroll
    for (int i = 0; i < 4; ++i) {
        const float2 p0 = unpk(acc2[i][0]);
        const float2 p1 = unpk(acc2[i][1]);
        v[i][0] = p0.x; v[i][1] = p0.y; v[i][2] = p1.x; v[i][3] = p1.y;
    }
#pragma unroll
    for (int jc = 0; jc < 4; ++jc) {
        const int n = nbase + j0 + jc;
        uint2 h;
        h.x = pkhf(v[0][jc], v[1][jc]);
        h.y = pkhf(v[2][jc], v[3][jc]);
        *(uint2*)(g_bh + (size_t)n * NN + m0 + r0) = h;
    }
}

// ---------------------------------------------------------------------------
// Kernel 2: fp16 HMMA GEMM (exact R9 mainloop) + FUSED band epilogue.
// The 2nd CTA to finish band mi combines both partials (commutative add ->
// deterministic), applies bias+PReLU, writes g_h, band colsums; the last
// band overall computes wc inline.
// ---------------------------------------------------------------------------
__global__ void __launch_bounds__(256, 2)
gemm_mma(const float* __restrict__ adj, const float* __restrict__ bias,
         const float* __restrict__ alphap, const float* __restrict__ msk,
         const float* __restrict__ disc_w) {
    extern __shared__ char dyn[];
    const uint32_t sbase = (smem_u32(dyn) + 127u) & ~127u;

    const int tid = threadIdx.x;
    const int wid = tid >> 5;
    const int lane = tid & 31;
    const int mi = blockIdx.x >> 1;
    const int kh = blockIdx.x & 1;
    const int m0 = mi * BM;
    const size_t kbase = (size_t)kh * KHALF;

    const int wm = (wid & 1) * 32;
    const int wn = (wid >> 1) * 32;

    const int arow = tid >> 3;
    const float* aptr = adj + (size_t)(m0 + arow) * NN + kbase + (tid & 7) * 4;
    const uint32_t a_sts = (uint32_t)(arow * ROWB + (tid & 7) * 8);
    const int brow = tid >> 2;
    const unsigned short* bptr = g_bh + (size_t)brow * NN + kbase + (tid & 3) * 8;
    const uint32_t b_sts = (uint32_t)(brow * ROWB + (tid & 3) * 16);

    const uint32_t a_ld = (uint32_t)((wm + (lane & 15)) * ROWB + (lane >> 4) * 16);
    const uint32_t b_ld = (uint32_t)((wn + ((lane >> 4) << 3) + (lane & 7)) * ROWB
                                     + ((lane >> 3) & 1) * 16);

    float acc[2][4][4];
#pragma unroll
    for (int i = 0; i < 2; ++i)
#pragma unroll
        for (int j = 0; j < 4; ++j)
#pragma unroll
            for (int q = 0; q < 4; ++q) acc[i][j][q] = 0.f;

    float4 av[2][2];

    auto BCP = [&](int t) {
        const uint32_t st = sbase + (t % NSTG) * STAGE;
        const unsigned short* bp = bptr + (size_t)t * BKk;
#pragma unroll
        for (int p = 0; p < 2; ++p)
            cpa16(st + OB + b_sts + p * (64 * ROWB), bp + (size_t)p * 64 * NN);
    };
    auto ALDG = [&](int t, int set) {
        const float* ap = aptr + (size_t)t * BKk;
#pragma unroll
        for (int p = 0; p < 2; ++p)
            av[set][p] = *(const float4*)(ap + (size_t)p * 32 * NN);
    };
    auto ASTS = [&](int t, int set) {
        const uint32_t st = sbase + (t % NSTG) * STAGE;
#pragma unroll
        for (int p = 0; p < 2; ++p) {
            uint32_t w0 = pkhf(av[set][p].x * ASCALE, av[set][p].y * ASCALE);
            uint32_t w1 = pkhf(av[set][p].z * ASCALE, av[set][p].w * ASCALE);
            sts64(st + OA + a_sts + p * (32 * ROWB), w0, w1);
        }
    };
    auto COMPUTE = [&](int t) {
        const uint32_t st = sbase + (t % NSTG) * STAGE;
#pragma unroll
        for (int ks = 0; ks < 2; ++ks) {
            uint32_t ah[2][4];
            ldm4(ah[0], st + OA + a_ld + ks * 32);
            ldm4(ah[1], st + OA + a_ld + 16 * ROWB + ks * 32);
#pragma unroll
            for (int jp = 0; jp < 2; ++jp) {
                uint32_t b[4];
                ldm4(b, st + OB + b_ld + jp * (16 * ROWB) + ks * 32);
                mma16816(acc[0][2 * jp],     ah[0], b[0], b[1]);
                mma16816(acc[0][2 * jp + 1], ah[0], b[2], b[3]);
                mma16816(acc[1][2 * jp],     ah[1], b[0], b[1]);
                mma16816(acc[1][2 * jp + 1], ah[1], b[2], b[3]);
            }
        }
    };

    BCP(0); cp_commit();
    BCP(1); cp_commit();
    ALDG(0, 0);
    ALDG(1, 1);
    ASTS(0, 0);
    cp_wait1();
    __syncthreads();

    int cur = 1;
    for (int t = 0; t < NT; ++t) {
        if (t + 2 < NT) BCP(t + 2);
        cp_commit();
        if (t + 2 < NT) ALDG(t + 2, cur ^ 1);
        COMPUTE(t);
        if (t + 1 < NT) ASTS(t + 1, cur);
        cp_wait1();
        __syncthreads();
        cur ^= 1;
    }

    // write raw (scaled) partials
    float* gacc = (kh ? g_acc1 : g_acc0);
    const int r0 = m0 + wm + (lane >> 2);
    const int cb = wn + (lane & 3) * 2;
#pragma unroll
    for (int i = 0; i < 2; ++i) {
#pragma unroll
        for (int j = 0; j < 4; ++j) {
            const int rr = r0 + i * 16;
            const int col = cb + j * 8;
            *(float2*)&gacc[(size_t)rr * HC + col] =
                make_float2(acc[i][j][0], acc[i][j][1]);
            *(float2*)&gacc[(size_t)(rr + 8) * HC + col] =
                make_float2(acc[i][j][2], acc[i][j][3]);
        }
    }

    // ---- band completion ticket ----
    __shared__ int tick_s;
    if (tid == 0) {
        __threadfence();
        tick_s = atomicAdd(&g_bandctr[mi], 1);
    }
    __syncthreads();
    if (tick_s == 0) return;        // first finisher: done

    // ---- band epilogue (2nd finisher): h = PReLU((p0+p1)/8192 + bias) ----
    // smem reuse of dyn (all GEMM use finished; barrier above synchronizes)
    float* e_sp  = (float*)dyn;             // [2][64]
    float* e_sm  = (float*)(dyn + 512);     // [64]
    const int c = tid & 127, rg2 = tid >> 7;
    const float alpha = __ldg(alphap);
    const float bi = __ldg(&bias[c & 63]);

    float csum = 0.f;
#pragma unroll 4
    for (int i = 0; i < 32; ++i) {
        const int n = m0 + rg2 + 2 * i;
        const size_t idx = (size_t)n * HC + c;
        float v = (g_acc0[idx] + g_acc1[idx]) * ASCALE_I + bi;
        v = v > 0.f ? v : alpha * v;
        g_h[idx] = v;
        csum += msk[n] * v;         // meaningful for c<64 (h1)
    }
    if (c < 64) e_sp[rg2 * 64 + c] = csum;
    if (tid < 64) e_sm[tid] = msk[m0 + tid];
    __syncthreads();

    if (tid < 64) g_part[mi * 64 + tid] = e_sp[tid] + e_sp[64 + tid];
    if (tid < 32) {
        float m = e_sm[tid] + e_sm[tid + 32];
#pragma unroll
        for (int o = 16; o; o >>= 1) m += __shfl_down_sync(0xffffffffu, m, o);
        if (tid == 0) g_mskpart[mi] = m;
    }
    __syncthreads();

    // ---- global ticket: last band computes wc ----
    __shared__ int last_s;
    if (tid == 0) {
        __threadfence();
        last_s = (atomicAdd(&g_epictr, 1) == NBANDS - 1);
    }
    __syncthreads();
    if (!last_s) return;

    float* e_red  = (float*)(dyn + 1024);   // [4][64]
    float* e_cvec = (float*)(dyn + 2048);   // [64]
    float* e_msum = (float*)(dyn + 2304);   // [1]
    {
        const int g = tid >> 6, col = tid & 63;
        float s = 0.f;
#pragma unroll
        for (int bb = 0; bb < 32; ++bb) s += g_part[(g * 32 + bb) * 64 + col];
        e_red[g * 64 + col] = s;
        if (tid < 32) {
            float m = 0.f;
#pragma unroll
            for (int bb = 0; bb < 4; ++bb) m += g_mskpart[tid + bb * 32];
#pragma unroll
            for (int o = 16; o; o >>= 1) m += __shfl_down_sync(0xffffffffu, m, o);
            if (tid == 0) e_msum[0] = m;
        }
        __syncthreads();
        if (tid < 64) {
            float cv = (e_red[tid] + e_red[64 + tid] + e_red[128 + tid]
                        + e_red[192 + tid]) / e_msum[0];
            e_cvec[tid] = 1.f / (1.f + expf(-cv));
        }
        __syncthreads();
        const int j = tid >> 2, q = tid & 3;
        float r = 0.f;
#pragma unroll
        for (int k = 0; k < 16; ++k)
            r += disc_w[j * 64 + q * 16 + k] * e_cvec[q * 16 + k];
        r += __shfl_down_sync(0xffffffffu, r, 2);
        r += __shfl_down_sync(0xffffffffu, r, 1);
        if (q == 0) g_wc[j] = r;
    }
}

// ---------------------------------------------------------------------------
// Kernel 3: out[n] = h1[n,:].wc + b ; out[N+n] = h2[n,:].wc + b
// ---------------------------------------------------------------------------
__global__ void __launch_bounds__(256) scores(const float* __restrict__ db,
                                              float* __restrict__ out) {
    const int warp = threadIdx.x >> 5, lane = threadIdx.x & 31;
    const int n = blockIdx.x * 8 + warp;
    const float2* hp = (const float2*)(g_h + (size_t)n * HC);
    const float2 w2 = ((const float2*)g_wc)[lane];
    const float2 v1 = hp[lane];
    const float2 v2 = hp[32 + lane];
    float s1 = v1.x * w2.x + v1.y * w2.y;
    float s2 = v2.x * w2.x + v2.y * w2.y;
#pragma unroll
    for (int o = 16; o; o >>= 1) {
        s1 += __shfl_down_sync(0xffffffffu, s1, o);
        s2 += __shfl_down_sync(0xffffffffu, s2, o);
    }
    if (lane == 0) {
        const float bb = __ldg(db);
        out[n] = s1 + bb;
        out[NN + n] = s2 + bb;
    }
}

// ---------------------------------------------------------------------------
// Inputs: seq1, seq2, adj, msk, fc_w, gcn_bias, prelu_alpha, disc_w, disc_b
// Output: [1, 2N] float32
// ---------------------------------------------------------------------------
extern "C" void kernel_launch(void* const* d_in, const int* in_sizes, int n_in,
                              void* d_out, int out_size) {
    const float* seq1  = (const float*)d_in[0];
    const float* seq2  = (const float*)d_in[1];
    const float* adj   = (const float*)d_in[2];
    const float* msk   = (const float*)d_in[3];
    const float* fcw   = (const float*)d_in[4];
    const float* gbias = (const float*)d_in[5];
    const float* alpha = (const float*)d_in[6];
    const float* discw = (const float*)d_in[7];
    const float* discb = (const float*)d_in[8];
    float* out = (float*)d_out;

    cudaFuncSetAttribute(gemm_mma, cudaFuncAttributeMaxDynamicSharedMemorySize,
                         DYN_SMEM);

    fts_kernel<<<NN / 16, 128>>>(seq1, seq2, fcw);
    gemm_mma<<<(NN / BM) * 2, 256, DYN_SMEM>>>(adj, gbias, alpha, msk, discw);
    scores<<<NN / 8, 256>>>(discb, out);
}

// round 17
// speedup vs baseline: 1.2416x; 1.2416x over previous
#include <cuda_runtime.h>
#include <cuda_fp16.h>
#include <cstdint>
#include <cstddef>

// ---------------------------------------------------------------------------
// Problem constants
// ---------------------------------------------------------------------------
constexpr int NN  = 8192;   // nodes
constexpr int FIN = 256;    // input features
constexpr int HC  = 128;    // fused hidden columns (h1 | h2)

// Main GEMM tiling (R9-validated, DO NOT TOUCH): BM=64 BN=128 BK=32, 256 thr
constexpr int BM = 64, BN = 128, BKk = 32;
constexpr int KHALF = NN / 2;           // 4096
constexpr int NT = KHALF / BKk;         // 128 iters
constexpr int NBANDS = NN / BM;         // 128 row bands
constexpr int ROWB = 80;                // padded smem row stride (bytes)
constexpr int OA = 0;
constexpr int OB = BM * ROWB;           // 5120
constexpr int STAGE = OB + BN * ROWB;   // 15360 bytes / stage
constexpr int NSTG = 3;
constexpr int DYN_SMEM = NSTG * STAGE + 256;

// fts GEMM tiling: 64 m-rows x 64 n x K=256 per CTA, 128 threads / 4 warps
constexpr int F_NT   = FIN / 32;        // 8 k-chunks
constexpr int F_ASTG = 64 * ROWB;       // 5120 bytes per A stage
constexpr int F_OW   = 2 * F_ASTG;      // W tiles start after 2 A stages
constexpr int F_WSTG = 64 * ROWB;       // 5120 bytes per W chunk
constexpr int F_SMEM = F_OW + F_NT * F_WSTG + 256;  // ~51.5 KB

constexpr float ASCALE   = 8192.0f;     // exact pow2: adj*ASCALE in (0,1) fp16
constexpr float ASCALE_I = 1.0f / 8192.0f;

// ---------------------------------------------------------------------------
// Device scratch (allocation-free per harness rules)
// ---------------------------------------------------------------------------
__device__ unsigned short g_bh[HC * NN];    // fts^T fp16 [n][k]
__device__ float g_acc0[NN * HC];           // K-half 0 partial (scaled by 8192)
__device__ float g_acc1[NN * HC];           // K-half 1 partial
__device__ float g_h[NN * HC];              // h1|h2 after bias+PReLU
__device__ float g_part[128 * 64];          // per-band colsums of h1*msk
__device__ float g_mskpart[128];            // per-band msk sums
__device__ float g_wc[64];                  // disc_w @ sigmoid(c)
__device__ int   g_bandctr[NBANDS];         // per-band completion tickets
__device__ int   g_epictr;                  // global band-epilogue ticket

// ---------------------------------------------------------------------------
// Helpers (baseline PTX only — compute_103 virtual target safe)
// ---------------------------------------------------------------------------
__device__ __forceinline__ uint32_t smem_u32(const void* p) {
    uint32_t r;
    asm("{ .reg .u64 t; cvta.to.shared.u64 t, %1; cvt.u32.u64 %0, t; }"
        : "=r"(r) : "l"(p));
    return r;
}
__device__ __forceinline__ uint32_t pkhf(float lo, float hi) {
    __half2 h = __floats2half2_rn(lo, hi);
    return *reinterpret_cast<uint32_t*>(&h);
}
__device__ __forceinline__ void sts64(uint32_t addr, uint32_t a, uint32_t b) {
    asm volatile("st.shared.v2.b32 [%0], {%1, %2};"
                 :: "r"(addr), "r"(a), "r"(b) : "memory");
}
__device__ __forceinline__ void sts128(uint32_t addr, uint32_t a, uint32_t b,
                                       uint32_t c, uint32_t d) {
    asm volatile("st.shared.v4.b32 [%0], {%1, %2, %3, %4};"
                 :: "r"(addr), "r"(a), "r"(b), "r"(c), "r"(d) : "memory");
}
__device__ __forceinline__ void ldm4(uint32_t* r, uint32_t addr) {
    asm volatile("ldmatrix.sync.aligned.m8n8.x4.shared.b16 {%0,%1,%2,%3}, [%4];"
                 : "=r"(r[0]), "=r"(r[1]), "=r"(r[2]), "=r"(r[3]) : "r"(addr));
}
__device__ __forceinline__ void mma16816(float* c, const uint32_t* a,
                                         uint32_t b0, uint32_t b1) {
    asm volatile(
        "mma.sync.aligned.m16n8k16.row.col.f32.f16.f16.f32 "
        "{%0,%1,%2,%3}, {%4,%5,%6,%7}, {%8,%9}, {%0,%1,%2,%3};"
        : "+f"(c[0]), "+f"(c[1]), "+f"(c[2]), "+f"(c[3])
        : "r"(a[0]), "r"(a[1]), "r"(a[2]), "r"(a[3]), "r"(b0), "r"(b1));
}
__device__ __forceinline__ void cpa16(uint32_t dst, const void* src) {
    asm volatile("cp.async.cg.shared.global [%0], [%1], 16;"
                 :: "r"(dst), "l"(src));
}
__device__ __forceinline__ void cp_commit() {
    asm volatile("cp.async.commit_group;" ::: "memory");
}
__device__ __forceinline__ void cp_wait1() {
    asm volatile("cp.async.wait_group 1;" ::: "memory");
}

// ---------------------------------------------------------------------------
// Kernel 1: fts via tensor cores. CTA = (mi, s): 64 rows of seq_s, all 64
// hidden cols, K=256. Reuses the validated gemm fragment layout. Output is
// transposed through smem into g_bh[n][k] (n = s*64 + col, k = m).
// Also resets tickets (stream-ordered before gemm).
// ---------------------------------------------------------------------------
__global__ void __launch_bounds__(128, 2) fts_mma(
    const float* __restrict__ seq1, const float* __restrict__ seq2,
    const float* __restrict__ fcw) {
    extern __shared__ char dyn[];
    const uint32_t sb = (smem_u32(dyn) + 127u) & ~127u;

    const int tid = threadIdx.x;
    const int wid = tid >> 5;
    const int lane = tid & 31;
    const int mi = blockIdx.x >> 1;
    const int s = blockIdx.x & 1;
    const int m0 = mi * 64;
    const int nb = s * 64;
    const float* seq = s ? seq2 : seq1;

    if (blockIdx.x == 0) {
        if (tid == 0) g_epictr = 0;
        if (tid < NBANDS) g_bandctr[tid] = 0;
    }

    // --- W preload: fcw[64][256] fp32 -> fp16 smem chunks [t][n][32k] ---
    for (int p = 0; p < 32; ++p) {
        const int idx = p * 128 + tid;      // 4096 float4 total
        const int n = idx >> 6;             // 64 float4 per row
        const int rem = idx & 63;
        const int t = rem >> 3;
        const int q = rem & 7;
        const float4 v = *(const float4*)(fcw + n * FIN + t * 32 + q * 4);
        sts64(sb + F_OW + t * F_WSTG + n * ROWB + q * 8,
              pkhf(v.x, v.y), pkhf(v.z, v.w));
    }

    const int wm = (wid & 1) * 32;
    const int wn = (wid >> 1) * 32;

    // A producer: 2 lanes per 64-row; 16 floats each
    const int arow = tid >> 1;
    const int acl = tid & 1;
    const float* aptr = seq + (size_t)(m0 + arow) * FIN + acl * 16;
    const uint32_t a_sts = (uint32_t)(arow * ROWB + acl * 32);

    const uint32_t a_ld = (uint32_t)((wm + (lane & 15)) * ROWB + (lane >> 4) * 16);
    const uint32_t b_ld = (uint32_t)((wn + ((lane >> 4) << 3) + (lane & 7)) * ROWB
                                     + ((lane >> 3) & 1) * 16);

    float acc[2][4][4];
#pragma unroll
    for (int i = 0; i < 2; ++i)
#pragma unroll
        for (int j = 0; j < 4; ++j)
#pragma unroll
            for (int q = 0; q < 4; ++q) acc[i][j][q] = 0.f;

    float4 av[2][4];

    auto ALDG = [&](int t, int set) {
        const float4* ap = (const float4*)(aptr + (size_t)t * 32);
#pragma unroll
        for (int q = 0; q < 4; ++q) av[set][q] = ap[q];
    };
    auto ASTS = [&](int t, int set) {
        const uint32_t st = sb + (t & 1) * F_ASTG;
        uint32_t w[8];
#pragma unroll
        for (int q = 0; q < 4; ++q) {
            w[2 * q]     = pkhf(av[set][q].x, av[set][q].y);
            w[2 * q + 1] = pkhf(av[set][q].z, av[set][q].w);
        }
        sts128(st + a_sts,      w[0], w[1], w[2], w[3]);
        sts128(st + a_sts + 16, w[4], w[5], w[6], w[7]);
    };
    auto COMPUTE = [&](int t) {
        const uint32_t stA = sb + (t & 1) * F_ASTG;
        const uint32_t stW = sb + F_OW + t * F_WSTG;
#pragma unroll
        for (int ks = 0; ks < 2; ++ks) {
            uint32_t ah[2][4];
            ldm4(ah[0], stA + a_ld + ks * 32);
            ldm4(ah[1], stA + a_ld + 16 * ROWB + ks * 32);
#pragma unroll
            for (int jp = 0; jp < 2; ++jp) {
                uint32_t b[4];
                ldm4(b, stW + b_ld + jp * (16 * ROWB) + ks * 32);
                mma16816(acc[0][2 * jp],     ah[0], b[0], b[1]);
                mma16816(acc[0][2 * jp + 1], ah[0], b[2], b[3]);
                mma16816(acc[1][2 * jp],     ah[1], b[0], b[1]);
                mma16816(acc[1][2 * jp + 1], ah[1], b[2], b[3]);
            }
        }
    };

    ALDG(0, 0);
    ASTS(0, 0);
    __syncthreads();    // publishes W tiles + A stage 0

    for (int t = 0; t < F_NT; ++t) {
        const int nset = (t + 1) & 1;
        if (t + 1 < F_NT) ALDG(t + 1, nset);
        COMPUTE(t);
        if (t + 1 < F_NT) ASTS(t + 1, nset);
        __syncthreads();
    }

    // --- transpose through smem: [n 64][m 64] fp16, stride 72 ---
    __half* tb = (__half*)dyn;
#pragma unroll
    for (int i = 0; i < 2; ++i) {
#pragma unroll
        for (int j = 0; j < 4; ++j) {
            const int n_l = wn + (lane & 3) * 2 + j * 8;
            const int m_l = wm + (lane >> 2) + i * 16;
            tb[n_l * 72 + m_l]           = __float2half_rn(acc[i][j][0]);
            tb[(n_l + 1) * 72 + m_l]     = __float2half_rn(acc[i][j][1]);
            tb[n_l * 72 + m_l + 8]       = __float2half_rn(acc[i][j][2]);
            tb[(n_l + 1) * 72 + m_l + 8] = __float2half_rn(acc[i][j][3]);
        }
    }
    __syncthreads();

    // coalesced copy out: 2 threads per n-row, 32 fp16 (64B) each
    // (R16 bug fix: copy ALL 4 uint4 — previously only 2 were copied,
    //  leaving half of g_bh unwritten)
    {
        const int n_l = tid >> 1;
        const int hf = tid & 1;
        const uint4* src = (const uint4*)(tb + n_l * 72 + hf * 32);
        uint4* dst = (uint4*)(g_bh + (size_t)(nb + n_l) * NN + m0 + hf * 32);
        dst[0] = src[0];
        dst[1] = src[1];
        dst[2] = src[2];
        dst[3] = src[3];
    }
}

// ---------------------------------------------------------------------------
// Kernel 2: fp16 HMMA GEMM (exact R9 mainloop) + FUSED band epilogue
// (validated R15). 2nd CTA of each band does bias+PReLU+colsums; last band
// computes wc inline.
// ---------------------------------------------------------------------------
__global__ void __launch_bounds__(256, 2)
gemm_mma(const float* __restrict__ adj, const float* __restrict__ bias,
         const float* __restrict__ alphap, const float* __restrict__ msk,
         const float* __restrict__ disc_w) {
    extern __shared__ char dyn[];
    const uint32_t sbase = (smem_u32(dyn) + 127u) & ~127u;

    const int tid = threadIdx.x;
    const int wid = tid >> 5;
    const int lane = tid & 31;
    const int mi = blockIdx.x >> 1;
    const int kh = blockIdx.x & 1;
    const int m0 = mi * BM;
    const size_t kbase = (size_t)kh * KHALF;

    const int wm = (wid & 1) * 32;
    const int wn = (wid >> 1) * 32;

    const int arow = tid >> 3;
    const float* aptr = adj + (size_t)(m0 + arow) * NN + kbase + (tid & 7) * 4;
    const uint32_t a_sts = (uint32_t)(arow * ROWB + (tid & 7) * 8);
    const int brow = tid >> 2;
    const unsigned short* bptr = g_bh + (size_t)brow * NN + kbase + (tid & 3) * 8;
    const uint32_t b_sts = (uint32_t)(brow * ROWB + (tid & 3) * 16);

    const uint32_t a_ld = (uint32_t)((wm + (lane & 15)) * ROWB + (lane >> 4) * 16);
    const uint32_t b_ld = (uint32_t)((wn + ((lane >> 4) << 3) + (lane & 7)) * ROWB
                                     + ((lane >> 3) & 1) * 16);

    float acc[2][4][4];
#pragma unroll
    for (int i = 0; i < 2; ++i)
#pragma unroll
        for (int j = 0; j < 4; ++j)
#pragma unroll
            for (int q = 0; q < 4; ++q) acc[i][j][q] = 0.f;

    float4 av[2][2];

    auto BCP = [&](int t) {
        const uint32_t st = sbase + (t % NSTG) * STAGE;
        const unsigned short* bp = bptr + (size_t)t * BKk;
#pragma unroll
        for (int p = 0; p < 2; ++p)
            cpa16(st + OB + b_sts + p * (64 * ROWB), bp + (size_t)p * 64 * NN);
    };
    auto ALDG = [&](int t, int set) {
        const float* ap = aptr + (size_t)t * BKk;
#pragma unroll
        for (int p = 0; p < 2; ++p)
            av[set][p] = *(const float4*)(ap + (size_t)p * 32 * NN);
    };
    auto ASTS = [&](int t, int set) {
        const uint32_t st = sbase + (t % NSTG) * STAGE;
#pragma unroll
        for (int p = 0; p < 2; ++p) {
            uint32_t w0 = pkhf(av[set][p].x * ASCALE, av[set][p].y * ASCALE);
            uint32_t w1 = pkhf(av[set][p].z * ASCALE, av[set][p].w * ASCALE);
            sts64(st + OA + a_sts + p * (32 * ROWB), w0, w1);
        }
    };
    auto COMPUTE = [&](int t) {
        const uint32_t st = sbase + (t % NSTG) * STAGE;
#pragma unroll
        for (int ks = 0; ks < 2; ++ks) {
            uint32_t ah[2][4];
            ldm4(ah[0], st + OA + a_ld + ks * 32);
            ldm4(ah[1], st + OA + a_ld + 16 * ROWB + ks * 32);
#pragma unroll
            for (int jp = 0; jp < 2; ++jp) {
                uint32_t b[4];
                ldm4(b, st + OB + b_ld + jp * (16 * ROWB) + ks * 32);
                mma16816(acc[0][2 * jp],     ah[0], b[0], b[1]);
                mma16816(acc[0][2 * jp + 1], ah[0], b[2], b[3]);
                mma16816(acc[1][2 * jp],     ah[1], b[0], b[1]);
                mma16816(acc[1][2 * jp + 1], ah[1], b[2], b[3]);
            }
        }
    };

    BCP(0); cp_commit();
    BCP(1); cp_commit();
    ALDG(0, 0);
    ALDG(1, 1);
    ASTS(0, 0);
    cp_wait1();
    __syncthreads();

    int cur = 1;
    for (int t = 0; t < NT; ++t) {
        if (t + 2 < NT) BCP(t + 2);
        cp_commit();
        if (t + 2 < NT) ALDG(t + 2, cur ^ 1);
        COMPUTE(t);
        if (t + 1 < NT) ASTS(t + 1, cur);
        cp_wait1();
        __syncthreads();
        cur ^= 1;
    }

    float* gacc = (kh ? g_acc1 : g_acc0);
    const int r0 = m0 + wm + (lane >> 2);
    const int cb = wn + (lane & 3) * 2;
#pragma unroll
    for (int i = 0; i < 2; ++i) {
#pragma unroll
        for (int j = 0; j < 4; ++j) {
            const int rr = r0 + i * 16;
            const int col = cb + j * 8;
            *(float2*)&gacc[(size_t)rr * HC + col] =
                make_float2(acc[i][j][0], acc[i][j][1]);
            *(float2*)&gacc[(size_t)(rr + 8) * HC + col] =
                make_float2(acc[i][j][2], acc[i][j][3]);
        }
    }

    // ---- band completion ticket ----
    __shared__ int tick_s;
    if (tid == 0) {
        __threadfence();
        tick_s = atomicAdd(&g_bandctr[mi], 1);
    }
    __syncthreads();
    if (tick_s == 0) return;

    // ---- band epilogue (2nd finisher) ----
    float* e_sp  = (float*)dyn;             // [2][64]
    float* e_sm  = (float*)(dyn + 512);     // [64]
    const int c = tid & 127, rg2 = tid >> 7;
    const float alpha = __ldg(alphap);
    const float bi = __ldg(&bias[c & 63]);

    float csum = 0.f;
#pragma unroll 4
    for (int i = 0; i < 32; ++i) {
        const int n = m0 + rg2 + 2 * i;
        const size_t idx = (size_t)n * HC + c;
        float v = (g_acc0[idx] + g_acc1[idx]) * ASCALE_I + bi;
        v = v > 0.f ? v : alpha * v;
        g_h[idx] = v;
        csum += msk[n] * v;
    }
    if (c < 64) e_sp[rg2 * 64 + c] = csum;
    if (tid < 64) e_sm[tid] = msk[m0 + tid];
    __syncthreads();

    if (tid < 64) g_part[mi * 64 + tid] = e_sp[tid] + e_sp[64 + tid];
    if (tid < 32) {
        float m = e_sm[tid] + e_sm[tid + 32];
#pragma unroll
        for (int o = 16; o; o >>= 1) m += __shfl_down_sync(0xffffffffu, m, o);
        if (tid == 0) g_mskpart[mi] = m;
    }
    __syncthreads();

    __shared__ int last_s;
    if (tid == 0) {
        __threadfence();
        last_s = (atomicAdd(&g_epictr, 1) == NBANDS - 1);
    }
    __syncthreads();
    if (!last_s) return;

    float* e_red  = (float*)(dyn + 1024);   // [4][64]
    float* e_cvec = (float*)(dyn + 2048);   // [64]
    float* e_msum = (float*)(dyn + 2304);   // [1]
    {
        const int g = tid >> 6, col = tid & 63;
        float s = 0.f;
#pragma unroll
        for (int bb = 0; bb < 32; ++bb) s += g_part[(g * 32 + bb) * 64 + col];
        e_red[g * 64 + col] = s;
        if (tid < 32) {
            float m = 0.f;
#pragma unroll
            for (int bb = 0; bb < 4; ++bb) m += g_mskpart[tid + bb * 32];
#pragma unroll
            for (int o = 16; o; o >>= 1) m += __shfl_down_sync(0xffffffffu, m, o);
            if (tid == 0) e_msum[0] = m;
        }
        __syncthreads();
        if (tid < 64) {
            float cv = (e_red[tid] + e_red[64 + tid] + e_red[128 + tid]
                        + e_red[192 + tid]) / e_msum[0];
            e_cvec[tid] = 1.f / (1.f + expf(-cv));
        }
        __syncthreads();
        const int j = tid >> 2, q = tid & 3;
        float r = 0.f;
#pragma unroll
        for (int k = 0; k < 16; ++k)
            r += disc_w[j * 64 + q * 16 + k] * e_cvec[q * 16 + k];
        r += __shfl_down_sync(0xffffffffu, r, 2);
        r += __shfl_down_sync(0xffffffffu, r, 1);
        if (q == 0) g_wc[j] = r;
    }
}

// ---------------------------------------------------------------------------
// Kernel 3: out[n] = h1[n,:].wc + b ; out[N+n] = h2[n,:].wc + b
// ---------------------------------------------------------------------------
__global__ void __launch_bounds__(256) scores(const float* __restrict__ db,
                                              float* __restrict__ out) {
    const int warp = threadIdx.x >> 5, lane = threadIdx.x & 31;
    const int n = blockIdx.x * 8 + warp;
    const float2* hp = (const float2*)(g_h + (size_t)n * HC);
    const float2 w2 = ((const float2*)g_wc)[lane];
    const float2 v1 = hp[lane];
    const float2 v2 = hp[32 + lane];
    float s1 = v1.x * w2.x + v1.y * w2.y;
    float s2 = v2.x * w2.x + v2.y * w2.y;
#pragma unroll
    for (int o = 16; o; o >>= 1) {
        s1 += __shfl_down_sync(0xffffffffu, s1, o);
        s2 += __shfl_down_sync(0xffffffffu, s2, o);
    }
    if (lane == 0) {
        const float bb = __ldg(db);
        out[n] = s1 + bb;
        out[NN + n] = s2 + bb;
    }
}

// ---------------------------------------------------------------------------
// Inputs: seq1, seq2, adj, msk, fc_w, gcn_bias, prelu_alpha, disc_w, disc_b
// Output: [1, 2N] float32
// ---------------------------------------------------------------------------
extern "C" void kernel_launch(void* const* d_in, const int* in_sizes, int n_in,
                              void* d_out, int out_size) {
    const float* seq1  = (const float*)d_in[0];
    const float* seq2  = (const float*)d_in[1];
    const float* adj   = (const float*)d_in[2];
    const float* msk   = (const float*)d_in[3];
    const float* fcw   = (const float*)d_in[4];
    const float* gbias = (const float*)d_in[5];
    const float* alpha = (const float*)d_in[6];
    const float* discw = (const float*)d_in[7];
    const float* discb = (const float*)d_in[8];
    float* out = (float*)d_out;

    cudaFuncSetAttribute(fts_mma, cudaFuncAttributeMaxDynamicSharedMemorySize,
                         F_SMEM);
    cudaFuncSetAttribute(gemm_mma, cudaFuncAttributeMaxDynamicSharedMemorySize,
                         DYN_SMEM);

    fts_mma<<<NBANDS * 2, 128, F_SMEM>>>(seq1, seq2, fcw);
    gemm_mma<<<(NN / BM) * 2, 256, DYN_SMEM>>>(adj, gbias, alpha, msk, discw);
    scores<<<NN / 8, 256>>>(discb, out);
}